// round 1
// baseline (speedup 1.0000x reference)
#include <cuda_runtime.h>
#include <cstdint>

#define HW 3136

// Scratch (device globals: no runtime allocation allowed)
__device__ float g_mid1[16 * 128 * HW];
__device__ float g_mid2[16 * 128 * HW];
__device__ float g_sc1[128], g_bi1[128];
__device__ float g_sc2[128], g_bi2[128];
__device__ float g_sc3[512], g_bi3[512];

// ---------------------------------------------------------------------------
// Fold BN params into scale/bias
// ---------------------------------------------------------------------------
__global__ void bn_prep(const float* __restrict__ g1, const float* __restrict__ b1,
                        const float* __restrict__ m1, const float* __restrict__ v1,
                        const float* __restrict__ g2, const float* __restrict__ b2,
                        const float* __restrict__ m2, const float* __restrict__ v2,
                        const float* __restrict__ g3, const float* __restrict__ b3,
                        const float* __restrict__ m3, const float* __restrict__ v3) {
    int i = threadIdx.x;  // 512 threads
    if (i < 128) {
        float s = g1[i] * rsqrtf(v1[i] + 1e-5f);
        g_sc1[i] = s;
        g_bi1[i] = b1[i] - m1[i] * s;
        float s2 = g2[i] * rsqrtf(v2[i] + 1e-5f);
        g_sc2[i] = s2;
        g_bi2[i] = b2[i] - m2[i] * s2;
    }
    float s3 = g3[i] * rsqrtf(v3[i] + 1e-5f);
    g_sc3[i] = s3;
    g_bi3[i] = b3[i] - m3[i] * s3;
}

// ---------------------------------------------------------------------------
// K1: 1x1 grouped conv (128in -> 32out per group) + BN1 + ReLU + mask2 premult
// block = (b, g, 4-row tile of 224 pixels), 224 threads, each thread: 1 px x 32 oc
// ---------------------------------------------------------------------------
__global__ __launch_bounds__(224) void k1(const float* __restrict__ x,
                                          const float* __restrict__ mask,
                                          const float* __restrict__ w1) {
    __shared__ __align__(16) float ws[128 * 32];   // [ic][oc]
    __shared__ __align__(16) float xs[32 * 224];   // [ic_chunk][px]

    const int t = threadIdx.x;
    const int blk = blockIdx.x;
    const int rowblk = blk % 14;
    const int bg = blk / 14;
    const int g = bg & 3, b = bg >> 2;

    for (int e = t; e < 4096; e += 224) {
        int ic = e >> 5, oc = e & 31;
        ws[e] = w1[(g * 32 + oc) * 128 + ic];
    }

    const int row0 = rowblk * 4;
    float acc[32];
#pragma unroll
    for (int oc = 0; oc < 32; oc++) acc[oc] = 0.f;

    const float* xb = x + (size_t)(b * 512 + g * 128) * HW + row0 * 56;

    for (int ch = 0; ch < 4; ch++) {
        __syncthreads();
#pragma unroll
        for (int i = 0; i < 32; i++) xs[i * 224 + t] = xb[(size_t)(ch * 32 + i) * HW + t];
        __syncthreads();
#pragma unroll 8
        for (int i = 0; i < 32; i++) {
            float xv = xs[i * 224 + t];
            const float4* wp = (const float4*)(ws + (ch * 32 + i) * 32);
#pragma unroll
            for (int j = 0; j < 8; j++) {
                float4 w4 = wp[j];
                acc[4 * j + 0] = fmaf(xv, w4.x, acc[4 * j + 0]);
                acc[4 * j + 1] = fmaf(xv, w4.y, acc[4 * j + 1]);
                acc[4 * j + 2] = fmaf(xv, w4.z, acc[4 * j + 2]);
                acc[4 * j + 3] = fmaf(xv, w4.w, acc[4 * j + 3]);
            }
        }
    }

    const int row = row0 + t / 56;
    const int col = t % 56;
    const float m = mask[((b * 4 + g) * 7 + (row >> 3)) * 7 + (col >> 3)];

    float* op = g_mid1 + (size_t)(b * 128 + g * 32) * HW + row0 * 56 + t;
#pragma unroll
    for (int oc = 0; oc < 32; oc++) {
        float v = fmaf(m * acc[oc], g_sc1[g * 32 + oc], g_bi1[g * 32 + oc]);
        op[(size_t)oc * HW] = fmaxf(v, 0.f) * m;
    }
}

// ---------------------------------------------------------------------------
// K2: 3x3 grouped conv (32->32 per group, pad 1) + BN2 + ReLU + mask
// block = (b, g, 4-row tile), 224 threads; smem: weights[32][9][32] + halo tile [32][6][58]
// ---------------------------------------------------------------------------
__global__ __launch_bounds__(224) void k2(const float* __restrict__ mask,
                                          const float* __restrict__ w2) {
    extern __shared__ __align__(16) float sm[];
    float* ws = sm;            // 9216 floats: [ic][k][oc]
    float* xs = sm + 9216;     // 11136 floats: [ic][6][58]

    const int t = threadIdx.x;
    const int blk = blockIdx.x;
    const int rowblk = blk % 14;
    const int bg = blk / 14;
    const int g = bg & 3, b = bg >> 2;

    for (int e = t; e < 9216; e += 224) {
        int ic = e / 288;
        int k = (e >> 5) % 9;
        int oc = e & 31;
        ws[e] = w2[((g * 32 + oc) * 32 + ic) * 9 + k];
    }

    const int row0 = rowblk * 4;
    const float* mb = g_mid1 + (size_t)(b * 128 + g * 32) * HW;
    for (int e = t; e < 11136; e += 224) {
        int ic = e / 348;
        int rem = e - ic * 348;
        int r = rem / 58;
        int cx = rem - r * 58;
        int gy = row0 - 1 + r, gx = cx - 1;
        float v = 0.f;
        if (gy >= 0 && gy < 56 && gx >= 0 && gx < 56)
            v = mb[(size_t)ic * HW + gy * 56 + gx];
        xs[e] = v;
    }
    __syncthreads();

    const int ty = t / 56, tx = t % 56;
    float acc[32];
#pragma unroll
    for (int oc = 0; oc < 32; oc++) acc[oc] = 0.f;

#pragma unroll 1
    for (int ic = 0; ic < 32; ic++) {
        const float* xrow = xs + ic * 348 + ty * 58 + tx;
#pragma unroll
        for (int dy = 0; dy < 3; dy++) {
            float x0 = xrow[dy * 58 + 0];
            float x1 = xrow[dy * 58 + 1];
            float x2 = xrow[dy * 58 + 2];
            const float4* wp = (const float4*)(ws + (ic * 9 + dy * 3) * 32);
#pragma unroll
            for (int j = 0; j < 8; j++) {
                float4 wa = wp[j];
                float4 wb = wp[j + 8];
                float4 wc = wp[j + 16];
                acc[4 * j + 0] = fmaf(x0, wa.x, fmaf(x1, wb.x, fmaf(x2, wc.x, acc[4 * j + 0])));
                acc[4 * j + 1] = fmaf(x0, wa.y, fmaf(x1, wb.y, fmaf(x2, wc.y, acc[4 * j + 1])));
                acc[4 * j + 2] = fmaf(x0, wa.z, fmaf(x1, wb.z, fmaf(x2, wc.z, acc[4 * j + 2])));
                acc[4 * j + 3] = fmaf(x0, wa.w, fmaf(x1, wb.w, fmaf(x2, wc.w, acc[4 * j + 3])));
            }
        }
    }

    const int row = row0 + ty;
    const float m = mask[((b * 4 + g) * 7 + (row >> 3)) * 7 + (tx >> 3)];

    float* op = g_mid2 + (size_t)(b * 128 + g * 32) * HW + row0 * 56 + t;
#pragma unroll
    for (int oc = 0; oc < 32; oc++) {
        float v = fmaf(acc[oc], g_sc2[g * 32 + oc], g_bi2[g * 32 + oc]);
        op[(size_t)oc * HW] = fmaxf(v, 0.f) * m;
    }
}

// ---------------------------------------------------------------------------
// K3: 1x1 grouped conv (32in -> 128out per group) + BN3 + residual + ReLU
// block = (b, g, 4-row tile), 224 threads, 4 oc-quarter passes of 32 acc each
// ---------------------------------------------------------------------------
__global__ __launch_bounds__(224) void k3(const float* __restrict__ x,
                                          const float* __restrict__ w3,
                                          float* __restrict__ out) {
    __shared__ __align__(16) float ws[32 * 128];   // [ic][oc]
    __shared__ __align__(16) float xs[32 * 224];   // [ic][px]

    const int t = threadIdx.x;
    const int blk = blockIdx.x;
    const int rowblk = blk % 14;
    const int bg = blk / 14;
    const int g = bg & 3, b = bg >> 2;

    for (int e = t; e < 4096; e += 224) {
        int ic = e >> 7, oc = e & 127;
        ws[e] = w3[(g * 128 + oc) * 32 + ic];
    }

    const int row0 = rowblk * 4;
    const float* mb = g_mid2 + (size_t)(b * 128 + g * 32) * HW + row0 * 56;
#pragma unroll
    for (int i = 0; i < 32; i++) xs[i * 224 + t] = mb[(size_t)i * HW + t];
    __syncthreads();

    const float* resb = x + (size_t)(b * 512 + g * 128) * HW + row0 * 56 + t;
    float* ob = out + (size_t)(b * 512 + g * 128) * HW + row0 * 56 + t;

    for (int q = 0; q < 4; q++) {
        float acc[32];
#pragma unroll
        for (int oc = 0; oc < 32; oc++) acc[oc] = 0.f;
#pragma unroll 8
        for (int i = 0; i < 32; i++) {
            float xv = xs[i * 224 + t];
            const float4* wp = (const float4*)(ws + i * 128 + q * 32);
#pragma unroll
            for (int j = 0; j < 8; j++) {
                float4 w4 = wp[j];
                acc[4 * j + 0] = fmaf(xv, w4.x, acc[4 * j + 0]);
                acc[4 * j + 1] = fmaf(xv, w4.y, acc[4 * j + 1]);
                acc[4 * j + 2] = fmaf(xv, w4.z, acc[4 * j + 2]);
                acc[4 * j + 3] = fmaf(xv, w4.w, acc[4 * j + 3]);
            }
        }
#pragma unroll
        for (int oc = 0; oc < 32; oc++) {
            int c = q * 32 + oc;
            float v = fmaf(acc[oc], g_sc3[g * 128 + c], g_bi3[g * 128 + c]) + resb[(size_t)c * HW];
            ob[(size_t)c * HW] = fmaxf(v, 0.f);
        }
    }
}

// ---------------------------------------------------------------------------
extern "C" void kernel_launch(void* const* d_in, const int* in_sizes, int n_in,
                              void* d_out, int out_size) {
    const float* x    = (const float*)d_in[0];
    const float* mask = (const float*)d_in[1];
    const float* w1   = (const float*)d_in[2];
    const float* g1 = (const float*)d_in[3];
    const float* b1 = (const float*)d_in[4];
    const float* m1 = (const float*)d_in[5];
    const float* v1 = (const float*)d_in[6];
    const float* w2   = (const float*)d_in[7];
    const float* g2 = (const float*)d_in[8];
    const float* b2 = (const float*)d_in[9];
    const float* m2 = (const float*)d_in[10];
    const float* v2 = (const float*)d_in[11];
    const float* w3   = (const float*)d_in[12];
    const float* g3 = (const float*)d_in[13];
    const float* b3 = (const float*)d_in[14];
    const float* m3 = (const float*)d_in[15];
    const float* v3 = (const float*)d_in[16];
    float* out = (float*)d_out;

    bn_prep<<<1, 512>>>(g1, b1, m1, v1, g2, b2, m2, v2, g3, b3, m3, v3);

    const int blocks = 16 * 4 * 14;  // (b, g, 4-row tile)
    k1<<<blocks, 224>>>(x, mask, w1);

    const int k2_smem = (9216 + 11136) * (int)sizeof(float);  // 81408 B
    cudaFuncSetAttribute(k2, cudaFuncAttributeMaxDynamicSharedMemorySize, k2_smem);
    k2<<<blocks, 224, k2_smem>>>(mask, w2);

    k3<<<blocks, 224>>>(x, w3, out);
}

// round 2
// speedup vs baseline: 1.1392x; 1.1392x over previous
#include <cuda_runtime.h>
#include <cstdint>

#define HW 3136

// Scratch (device globals: no runtime allocation allowed)
__device__ float g_mid1[16 * 128 * HW];
__device__ float g_mid2[16 * 128 * HW];
__device__ float g_sc1[128], g_bi1[128];
__device__ float g_sc2[128], g_bi2[128];
__device__ float g_sc3[512], g_bi3[512];

// ---------------------------------------------------------------------------
// Fold BN params into scale/bias
// ---------------------------------------------------------------------------
__global__ void bn_prep(const float* __restrict__ g1, const float* __restrict__ b1,
                        const float* __restrict__ m1, const float* __restrict__ v1,
                        const float* __restrict__ g2, const float* __restrict__ b2,
                        const float* __restrict__ m2, const float* __restrict__ v2,
                        const float* __restrict__ g3, const float* __restrict__ b3,
                        const float* __restrict__ m3, const float* __restrict__ v3) {
    int i = threadIdx.x;  // 512 threads
    if (i < 128) {
        float s = g1[i] * rsqrtf(v1[i] + 1e-5f);
        g_sc1[i] = s;
        g_bi1[i] = b1[i] - m1[i] * s;
        float s2 = g2[i] * rsqrtf(v2[i] + 1e-5f);
        g_sc2[i] = s2;
        g_bi2[i] = b2[i] - m2[i] * s2;
    }
    float s3 = g3[i] * rsqrtf(v3[i] + 1e-5f);
    g_sc3[i] = s3;
    g_bi3[i] = b3[i] - m3[i] * s3;
}

// Common decode: block = (b, g, patch_row pr). 224 threads = 7 warps.
// warp w = patch column (0..6). lane: r = l>>2 (row in patch), cp = l&3 (col pair).
// Each thread owns 2 horizontally adjacent pixels.

// ---------------------------------------------------------------------------
// K1: 1x1 grouped conv (128 -> 32 per group) + BN1 + ReLU + mask premult
// ---------------------------------------------------------------------------
__global__ __launch_bounds__(224, 3) void k1(const float* __restrict__ x,
                                             const float* __restrict__ mask,
                                             const float* __restrict__ w1) {
    __shared__ __align__(16) float ws[4096];  // [ic][oc] 128x32

    const int t = threadIdx.x, blk = blockIdx.x;
    const int pr = blk % 7;
    const int bg = blk / 7;
    const int g = bg & 3, b = bg >> 2;

    // coalesced weight load, transposed store
    for (int e = t; e < 4096; e += 224) {
        int oc = e >> 7, ic = e & 127;
        ws[ic * 32 + oc] = w1[g * 4096 + e];
    }
    __syncthreads();

    const int w = t >> 5, l = t & 31;
    const int r = l >> 2, cp = l & 3;
    const int grow = pr * 8 + r;
    const int col = w * 8 + cp * 2;
    const float m = mask[((b * 4 + g) * 7 + pr) * 7 + w];

    float* op = g_mid1 + (size_t)(b * 128 + g * 32) * HW + grow * 56 + col;

    if (m != 0.f) {
        const float* xp = x + (size_t)(b * 512 + g * 128) * HW + grow * 56 + col;
        float a0[32], a1[32];
#pragma unroll
        for (int oc = 0; oc < 32; oc++) { a0[oc] = 0.f; a1[oc] = 0.f; }

#pragma unroll 2
        for (int ic = 0; ic < 128; ic++) {
            float2 xv = *(const float2*)(xp + (size_t)ic * HW);
            const float4* wp = (const float4*)(ws + ic * 32);
#pragma unroll
            for (int j = 0; j < 8; j++) {
                float4 q = wp[j];
                a0[4 * j + 0] = fmaf(xv.x, q.x, a0[4 * j + 0]);
                a0[4 * j + 1] = fmaf(xv.x, q.y, a0[4 * j + 1]);
                a0[4 * j + 2] = fmaf(xv.x, q.z, a0[4 * j + 2]);
                a0[4 * j + 3] = fmaf(xv.x, q.w, a0[4 * j + 3]);
                a1[4 * j + 0] = fmaf(xv.y, q.x, a1[4 * j + 0]);
                a1[4 * j + 1] = fmaf(xv.y, q.y, a1[4 * j + 1]);
                a1[4 * j + 2] = fmaf(xv.y, q.z, a1[4 * j + 2]);
                a1[4 * j + 3] = fmaf(xv.y, q.w, a1[4 * j + 3]);
            }
        }
#pragma unroll
        for (int oc = 0; oc < 32; oc++) {
            float s = g_sc1[g * 32 + oc], bb = g_bi1[g * 32 + oc];
            float v0 = fmaxf(fmaf(m * a0[oc], s, bb), 0.f) * m;
            float v1 = fmaxf(fmaf(m * a1[oc], s, bb), 0.f) * m;
            *(float2*)(op + (size_t)oc * HW) = make_float2(v0, v1);
        }
    } else {
        float2 z = make_float2(0.f, 0.f);
#pragma unroll
        for (int oc = 0; oc < 32; oc++) *(float2*)(op + (size_t)oc * HW) = z;
    }
}

// ---------------------------------------------------------------------------
// K2: 3x3 grouped conv (32 -> 32 per group, pad 1) + BN2 + ReLU + mask
// ---------------------------------------------------------------------------
__global__ __launch_bounds__(224, 2) void k2(const float* __restrict__ mask,
                                             const float* __restrict__ w2) {
    __shared__ __align__(16) float ws[9216];  // [ic][dy][dx][oc]

    const int t = threadIdx.x, blk = blockIdx.x;
    const int pr = blk % 7;
    const int bg = blk / 7;
    const int g = bg & 3, b = bg >> 2;

    for (int e = t; e < 9216; e += 224) {
        int oc = e / 288;
        int rem = e - oc * 288;
        int ic = rem / 9;
        int k = rem - ic * 9;
        int dy = k / 3, dx = k - dy * 3;
        ws[((ic * 3 + dy) * 3 + dx) * 32 + oc] = w2[g * 9216 + e];
    }
    __syncthreads();

    const int w = t >> 5, l = t & 31;
    const int r = l >> 2, cp = l & 3;
    const int grow = pr * 8 + r;
    const int col = w * 8 + cp * 2;
    const float m = mask[((b * 4 + g) * 7 + pr) * 7 + w];

    float* op = g_mid2 + (size_t)(b * 128 + g * 32) * HW + grow * 56 + col;

    if (m != 0.f) {
        const float* mb = g_mid1 + (size_t)(b * 128 + g * 32) * HW + col;
        float a0[32], a1[32];
#pragma unroll
        for (int oc = 0; oc < 32; oc++) { a0[oc] = 0.f; a1[oc] = 0.f; }

#pragma unroll 1
        for (int ic = 0; ic < 32; ic++) {
#pragma unroll
            for (int dy = 0; dy < 3; dy++) {
                int yy = grow - 1 + dy;
                if (yy >= 0 && yy < 56) {
                    const float* p = mb + (size_t)ic * HW + yy * 56;
                    float xm1 = (col > 0) ? p[-1] : 0.f;
                    float2 xc = *(const float2*)p;
                    float x2 = (col < 54) ? p[2] : 0.f;
                    const float4* wp = (const float4*)(ws + (ic * 9 + dy * 3) * 32);
#pragma unroll
                    for (int j = 0; j < 8; j++) {
                        float4 wa = wp[j];
                        float4 wb = wp[j + 8];
                        float4 wc = wp[j + 16];
                        a0[4 * j + 0] = fmaf(xm1, wa.x, fmaf(xc.x, wb.x, fmaf(xc.y, wc.x, a0[4 * j + 0])));
                        a0[4 * j + 1] = fmaf(xm1, wa.y, fmaf(xc.x, wb.y, fmaf(xc.y, wc.y, a0[4 * j + 1])));
                        a0[4 * j + 2] = fmaf(xm1, wa.z, fmaf(xc.x, wb.z, fmaf(xc.y, wc.z, a0[4 * j + 2])));
                        a0[4 * j + 3] = fmaf(xm1, wa.w, fmaf(xc.x, wb.w, fmaf(xc.y, wc.w, a0[4 * j + 3])));
                        a1[4 * j + 0] = fmaf(xc.x, wa.x, fmaf(xc.y, wb.x, fmaf(x2, wc.x, a1[4 * j + 0])));
                        a1[4 * j + 1] = fmaf(xc.x, wa.y, fmaf(xc.y, wb.y, fmaf(x2, wc.y, a1[4 * j + 1])));
                        a1[4 * j + 2] = fmaf(xc.x, wa.z, fmaf(xc.y, wb.z, fmaf(x2, wc.z, a1[4 * j + 2])));
                        a1[4 * j + 3] = fmaf(xc.x, wa.w, fmaf(xc.y, wb.w, fmaf(x2, wc.w, a1[4 * j + 3])));
                    }
                }
            }
        }
#pragma unroll
        for (int oc = 0; oc < 32; oc++) {
            float s = g_sc2[g * 32 + oc], bb = g_bi2[g * 32 + oc];
            float v0 = fmaxf(fmaf(a0[oc], s, bb), 0.f) * m;
            float v1 = fmaxf(fmaf(a1[oc], s, bb), 0.f) * m;
            *(float2*)(op + (size_t)oc * HW) = make_float2(v0, v1);
        }
    } else {
        float2 z = make_float2(0.f, 0.f);
#pragma unroll
        for (int oc = 0; oc < 32; oc++) *(float2*)(op + (size_t)oc * HW) = z;
    }
}

// ---------------------------------------------------------------------------
// K3: 1x1 grouped conv (32 -> 128 per group) + BN3 + residual + ReLU
// ---------------------------------------------------------------------------
__global__ __launch_bounds__(224, 3) void k3(const float* __restrict__ x,
                                             const float* __restrict__ mask,
                                             const float* __restrict__ w3,
                                             float* __restrict__ out) {
    __shared__ __align__(16) float ws[4096];  // [ic][oc] 32x128

    const int t = threadIdx.x, blk = blockIdx.x;
    const int pr = blk % 7;
    const int bg = blk / 7;
    const int g = bg & 3, b = bg >> 2;

    for (int e = t; e < 4096; e += 224) {
        int oc = e >> 5, ic = e & 31;
        ws[ic * 128 + oc] = w3[g * 4096 + e];
    }
    __syncthreads();

    const int w = t >> 5, l = t & 31;
    const int r = l >> 2, cp = l & 3;
    const int grow = pr * 8 + r;
    const int col = w * 8 + cp * 2;
    const float m = mask[((b * 4 + g) * 7 + pr) * 7 + w];

    const float* resp = x + (size_t)(b * 512 + g * 128) * HW + grow * 56 + col;
    float* op = out + (size_t)(b * 512 + g * 128) * HW + grow * 56 + col;

    if (m != 0.f) {
        const float* mp = g_mid2 + (size_t)(b * 128 + g * 32) * HW + grow * 56 + col;
        for (int q = 0; q < 4; q++) {
            float a0[32], a1[32];
#pragma unroll
            for (int oc = 0; oc < 32; oc++) { a0[oc] = 0.f; a1[oc] = 0.f; }
#pragma unroll 2
            for (int ic = 0; ic < 32; ic++) {
                float2 xv = *(const float2*)(mp + (size_t)ic * HW);
                const float4* wp = (const float4*)(ws + ic * 128 + q * 32);
#pragma unroll
                for (int j = 0; j < 8; j++) {
                    float4 qw = wp[j];
                    a0[4 * j + 0] = fmaf(xv.x, qw.x, a0[4 * j + 0]);
                    a0[4 * j + 1] = fmaf(xv.x, qw.y, a0[4 * j + 1]);
                    a0[4 * j + 2] = fmaf(xv.x, qw.z, a0[4 * j + 2]);
                    a0[4 * j + 3] = fmaf(xv.x, qw.w, a0[4 * j + 3]);
                    a1[4 * j + 0] = fmaf(xv.y, qw.x, a1[4 * j + 0]);
                    a1[4 * j + 1] = fmaf(xv.y, qw.y, a1[4 * j + 1]);
                    a1[4 * j + 2] = fmaf(xv.y, qw.z, a1[4 * j + 2]);
                    a1[4 * j + 3] = fmaf(xv.y, qw.w, a1[4 * j + 3]);
                }
            }
#pragma unroll
            for (int oc = 0; oc < 32; oc++) {
                int c = q * 32 + oc;
                float s = g_sc3[g * 128 + c], bb = g_bi3[g * 128 + c];
                float2 res = *(const float2*)(resp + (size_t)c * HW);
                float v0 = fmaxf(fmaf(a0[oc], s, bb) + res.x, 0.f);
                float v1 = fmaxf(fmaf(a1[oc], s, bb) + res.y, 0.f);
                *(float2*)(op + (size_t)c * HW) = make_float2(v0, v1);
            }
        }
    } else {
#pragma unroll 4
        for (int c = 0; c < 128; c++) {
            float bb = g_bi3[g * 128 + c];
            float2 res = *(const float2*)(resp + (size_t)c * HW);
            float v0 = fmaxf(bb + res.x, 0.f);
            float v1 = fmaxf(bb + res.y, 0.f);
            *(float2*)(op + (size_t)c * HW) = make_float2(v0, v1);
        }
    }
}

// ---------------------------------------------------------------------------
extern "C" void kernel_launch(void* const* d_in, const int* in_sizes, int n_in,
                              void* d_out, int out_size) {
    const float* x    = (const float*)d_in[0];
    const float* mask = (const float*)d_in[1];
    const float* w1   = (const float*)d_in[2];
    const float* g1 = (const float*)d_in[3];
    const float* b1 = (const float*)d_in[4];
    const float* m1 = (const float*)d_in[5];
    const float* v1 = (const float*)d_in[6];
    const float* w2   = (const float*)d_in[7];
    const float* g2 = (const float*)d_in[8];
    const float* b2 = (const float*)d_in[9];
    const float* m2 = (const float*)d_in[10];
    const float* v2 = (const float*)d_in[11];
    const float* w3   = (const float*)d_in[12];
    const float* g3 = (const float*)d_in[13];
    const float* b3 = (const float*)d_in[14];
    const float* m3 = (const float*)d_in[15];
    const float* v3 = (const float*)d_in[16];
    float* out = (float*)d_out;

    bn_prep<<<1, 512>>>(g1, b1, m1, v1, g2, b2, m2, v2, g3, b3, m3, v3);

    const int blocks = 16 * 4 * 7;  // (b, g, patch-row)
    k1<<<blocks, 224>>>(x, mask, w1);
    k2<<<blocks, 224>>>(mask, w2);
    k3<<<blocks, 224>>>(x, mask, w3, out);
}

// round 3
// speedup vs baseline: 2.2321x; 1.9594x over previous
#include <cuda_runtime.h>
#include <cstdint>

#define HW 3136

// Scratch (device globals: no runtime allocation allowed)
__device__ float g_mid1[16 * 128 * HW];
__device__ float g_mid2[16 * 128 * HW];
__device__ float g_sc1[128], g_bi1[128];
__device__ float g_sc2[128], g_bi2[128];
__device__ float g_sc3[512], g_bi3[512];

// ---------------------------------------------------------------------------
__global__ void bn_prep(const float* __restrict__ g1, const float* __restrict__ b1,
                        const float* __restrict__ m1, const float* __restrict__ v1,
                        const float* __restrict__ g2, const float* __restrict__ b2,
                        const float* __restrict__ m2, const float* __restrict__ v2,
                        const float* __restrict__ g3, const float* __restrict__ b3,
                        const float* __restrict__ m3, const float* __restrict__ v3) {
    int i = threadIdx.x;  // 512 threads
    if (i < 128) {
        float s = g1[i] * rsqrtf(v1[i] + 1e-5f);
        g_sc1[i] = s;
        g_bi1[i] = b1[i] - m1[i] * s;
        float s2 = g2[i] * rsqrtf(v2[i] + 1e-5f);
        g_sc2[i] = s2;
        g_bi2[i] = b2[i] - m2[i] * s2;
    }
    float s3 = g3[i] * rsqrtf(v3[i] + 1e-5f);
    g_sc3[i] = s3;
    g_bi3[i] = b3[i] - m3[i] * s3;
}

// Common decode: 224 threads = 7 warps; warp = patch column, lane: r=l>>2 row,
// cp=l&3 col-pair; thread owns 2 adjacent pixels. Mask is warp-uniform.

// ---------------------------------------------------------------------------
// K1: 1x1 conv (128 -> 16 oc per block) + BN1 + ReLU + mask premult
// grid = (b, g, pr, half)
// ---------------------------------------------------------------------------
__global__ __launch_bounds__(224, 4) void k1(const float* __restrict__ x,
                                             const float* __restrict__ mask,
                                             const float* __restrict__ w1) {
    __shared__ __align__(16) float ws[2048];  // [ic][16]

    const int t = threadIdx.x, blk = blockIdx.x;
    const int h = blk & 1;
    const int rest = blk >> 1;
    const int pr = rest % 7;
    const int bg = rest / 7;
    const int g = bg & 3, b = bg >> 2;

    for (int e = t; e < 2048; e += 224) {
        int j = e >> 7, ic = e & 127;
        ws[ic * 16 + j] = w1[(g * 32 + h * 16 + j) * 128 + ic];
    }
    __syncthreads();

    const int w = t >> 5, l = t & 31;
    const int r = l >> 2, cp = l & 3;
    const int grow = pr * 8 + r;
    const int col = w * 8 + cp * 2;
    const float m = mask[((b * 4 + g) * 7 + pr) * 7 + w];

    float* op = g_mid1 + (size_t)(b * 128 + g * 32 + h * 16) * HW + grow * 56 + col;

    if (m != 0.f) {
        const float* xp = x + (size_t)(b * 512 + g * 128) * HW + grow * 56 + col;
        float a0[16], a1[16];
#pragma unroll
        for (int j = 0; j < 16; j++) { a0[j] = 0.f; a1[j] = 0.f; }

        for (int ic0 = 0; ic0 < 128; ic0 += 8) {
            float2 xv[8];
#pragma unroll
            for (int u = 0; u < 8; u++)
                xv[u] = *(const float2*)(xp + (size_t)(ic0 + u) * HW);
#pragma unroll
            for (int u = 0; u < 8; u++) {
                const float4* wp = (const float4*)(ws + (ic0 + u) * 16);
#pragma unroll
                for (int j = 0; j < 4; j++) {
                    float4 q = wp[j];
                    a0[4 * j + 0] = fmaf(xv[u].x, q.x, a0[4 * j + 0]);
                    a0[4 * j + 1] = fmaf(xv[u].x, q.y, a0[4 * j + 1]);
                    a0[4 * j + 2] = fmaf(xv[u].x, q.z, a0[4 * j + 2]);
                    a0[4 * j + 3] = fmaf(xv[u].x, q.w, a0[4 * j + 3]);
                    a1[4 * j + 0] = fmaf(xv[u].y, q.x, a1[4 * j + 0]);
                    a1[4 * j + 1] = fmaf(xv[u].y, q.y, a1[4 * j + 1]);
                    a1[4 * j + 2] = fmaf(xv[u].y, q.z, a1[4 * j + 2]);
                    a1[4 * j + 3] = fmaf(xv[u].y, q.w, a1[4 * j + 3]);
                }
            }
        }
#pragma unroll
        for (int j = 0; j < 16; j++) {
            int c = h * 16 + j;
            float s = g_sc1[g * 32 + c], bb = g_bi1[g * 32 + c];
            float v0 = fmaxf(fmaf(m * a0[j], s, bb), 0.f) * m;
            float v1 = fmaxf(fmaf(m * a1[j], s, bb), 0.f) * m;
            *(float2*)(op + (size_t)j * HW) = make_float2(v0, v1);
        }
    } else {
        float2 z = make_float2(0.f, 0.f);
#pragma unroll
        for (int j = 0; j < 16; j++) *(float2*)(op + (size_t)j * HW) = z;
    }
}

// ---------------------------------------------------------------------------
// K2: 3x3 conv (32 -> 16 oc per block, pad 1) + BN2 + ReLU + mask
// grid = (b, g, pr, half)
// ---------------------------------------------------------------------------
__global__ __launch_bounds__(224, 3) void k2(const float* __restrict__ mask,
                                             const float* __restrict__ w2) {
    __shared__ __align__(16) float ws[4608];  // [ic][dy][dx][16]

    const int t = threadIdx.x, blk = blockIdx.x;
    const int h = blk & 1;
    const int rest = blk >> 1;
    const int pr = rest % 7;
    const int bg = rest / 7;
    const int g = bg & 3, b = bg >> 2;

    for (int e = t; e < 4608; e += 224) {
        int j = e / 288;
        int rem = e - j * 288;
        int ic = rem / 9;
        int k = rem - ic * 9;
        ws[(ic * 9 + k) * 16 + j] = w2[((g * 32 + h * 16 + j) * 32 + ic) * 9 + k];
    }
    __syncthreads();

    const int w = t >> 5, l = t & 31;
    const int r = l >> 2, cp = l & 3;
    const int grow = pr * 8 + r;
    const int col = w * 8 + cp * 2;
    const float m = mask[((b * 4 + g) * 7 + pr) * 7 + w];

    float* op = g_mid2 + (size_t)(b * 128 + g * 32 + h * 16) * HW + grow * 56 + col;

    if (m != 0.f) {
        const float* mb = g_mid1 + (size_t)(b * 128 + g * 32) * HW + col;
        float a0[16], a1[16];
#pragma unroll
        for (int j = 0; j < 16; j++) { a0[j] = 0.f; a1[j] = 0.f; }

#pragma unroll 2
        for (int ic = 0; ic < 32; ic++) {
            const float* pic = mb + (size_t)ic * HW;
            float xm[3], x2[3];
            float2 xc[3];
#pragma unroll
            for (int dy = 0; dy < 3; dy++) {
                int yy = grow - 1 + dy;
                bool v = (yy >= 0) && (yy < 56);
                const float* p = pic + yy * 56;
                xm[dy] = (v && col > 0) ? p[-1] : 0.f;
                xc[dy] = v ? *(const float2*)p : make_float2(0.f, 0.f);
                x2[dy] = (v && col < 54) ? p[2] : 0.f;
            }
#pragma unroll
            for (int dy = 0; dy < 3; dy++) {
                const float4* wp = (const float4*)(ws + (ic * 9 + dy * 3) * 16);
#pragma unroll
                for (int j = 0; j < 4; j++) {
                    float4 wa = wp[j];
                    float4 wb = wp[4 + j];
                    float4 wc = wp[8 + j];
                    float p0 = xm[dy], p1 = xc[dy].x, p2 = xc[dy].y, p3 = x2[dy];
                    a0[4 * j + 0] = fmaf(p0, wa.x, fmaf(p1, wb.x, fmaf(p2, wc.x, a0[4 * j + 0])));
                    a0[4 * j + 1] = fmaf(p0, wa.y, fmaf(p1, wb.y, fmaf(p2, wc.y, a0[4 * j + 1])));
                    a0[4 * j + 2] = fmaf(p0, wa.z, fmaf(p1, wb.z, fmaf(p2, wc.z, a0[4 * j + 2])));
                    a0[4 * j + 3] = fmaf(p0, wa.w, fmaf(p1, wb.w, fmaf(p2, wc.w, a0[4 * j + 3])));
                    a1[4 * j + 0] = fmaf(p1, wa.x, fmaf(p2, wb.x, fmaf(p3, wc.x, a1[4 * j + 0])));
                    a1[4 * j + 1] = fmaf(p1, wa.y, fmaf(p2, wb.y, fmaf(p3, wc.y, a1[4 * j + 1])));
                    a1[4 * j + 2] = fmaf(p1, wa.z, fmaf(p2, wb.z, fmaf(p3, wc.z, a1[4 * j + 2])));
                    a1[4 * j + 3] = fmaf(p1, wa.w, fmaf(p2, wb.w, fmaf(p3, wc.w, a1[4 * j + 3])));
                }
            }
        }
#pragma unroll
        for (int j = 0; j < 16; j++) {
            int c = h * 16 + j;
            float s = g_sc2[g * 32 + c], bb = g_bi2[g * 32 + c];
            float v0 = fmaxf(fmaf(a0[j], s, bb), 0.f) * m;
            float v1 = fmaxf(fmaf(a1[j], s, bb), 0.f) * m;
            *(float2*)(op + (size_t)j * HW) = make_float2(v0, v1);
        }
    } else {
        float2 z = make_float2(0.f, 0.f);
#pragma unroll
        for (int j = 0; j < 16; j++) *(float2*)(op + (size_t)j * HW) = z;
    }
}

// ---------------------------------------------------------------------------
// K3: 1x1 conv (32 -> 16 oc per block) + BN3 + residual + ReLU
// grid = (b, g, pr, qc in 0..7)
// ---------------------------------------------------------------------------
__global__ __launch_bounds__(224, 4) void k3(const float* __restrict__ x,
                                             const float* __restrict__ mask,
                                             const float* __restrict__ w3,
                                             float* __restrict__ out) {
    __shared__ __align__(16) float ws[512];  // [ic][16]

    const int t = threadIdx.x, blk = blockIdx.x;
    const int qc = blk & 7;
    const int rest = blk >> 3;
    const int pr = rest % 7;
    const int bg = rest / 7;
    const int g = bg & 3, b = bg >> 2;

    for (int e = t; e < 512; e += 224) {
        int j = e >> 5, ic = e & 31;
        ws[ic * 16 + j] = w3[(g * 128 + qc * 16 + j) * 32 + ic];
    }
    __syncthreads();

    const int w = t >> 5, l = t & 31;
    const int r = l >> 2, cp = l & 3;
    const int grow = pr * 8 + r;
    const int col = w * 8 + cp * 2;
    const float m = mask[((b * 4 + g) * 7 + pr) * 7 + w];

    const float* resp = x + (size_t)(b * 512 + g * 128 + qc * 16) * HW + grow * 56 + col;
    float* op = out + (size_t)(b * 512 + g * 128 + qc * 16) * HW + grow * 56 + col;

    if (m != 0.f) {
        const float* mp = g_mid2 + (size_t)(b * 128 + g * 32) * HW + grow * 56 + col;
        float a0[16], a1[16];
#pragma unroll
        for (int j = 0; j < 16; j++) { a0[j] = 0.f; a1[j] = 0.f; }

        for (int ic0 = 0; ic0 < 32; ic0 += 8) {
            float2 xv[8];
#pragma unroll
            for (int u = 0; u < 8; u++)
                xv[u] = *(const float2*)(mp + (size_t)(ic0 + u) * HW);
#pragma unroll
            for (int u = 0; u < 8; u++) {
                const float4* wp = (const float4*)(ws + (ic0 + u) * 16);
#pragma unroll
                for (int j = 0; j < 4; j++) {
                    float4 q = wp[j];
                    a0[4 * j + 0] = fmaf(xv[u].x, q.x, a0[4 * j + 0]);
                    a0[4 * j + 1] = fmaf(xv[u].x, q.y, a0[4 * j + 1]);
                    a0[4 * j + 2] = fmaf(xv[u].x, q.z, a0[4 * j + 2]);
                    a0[4 * j + 3] = fmaf(xv[u].x, q.w, a0[4 * j + 3]);
                    a1[4 * j + 0] = fmaf(xv[u].y, q.x, a1[4 * j + 0]);
                    a1[4 * j + 1] = fmaf(xv[u].y, q.y, a1[4 * j + 1]);
                    a1[4 * j + 2] = fmaf(xv[u].y, q.z, a1[4 * j + 2]);
                    a1[4 * j + 3] = fmaf(xv[u].y, q.w, a1[4 * j + 3]);
                }
            }
        }
#pragma unroll
        for (int j = 0; j < 16; j++) {
            int c = qc * 16 + j;
            float s = g_sc3[g * 128 + c], bb = g_bi3[g * 128 + c];
            float2 res = *(const float2*)(resp + (size_t)j * HW);
            float v0 = fmaxf(fmaf(a0[j], s, bb) + res.x, 0.f);
            float v1 = fmaxf(fmaf(a1[j], s, bb) + res.y, 0.f);
            *(float2*)(op + (size_t)j * HW) = make_float2(v0, v1);
        }
    } else {
#pragma unroll
        for (int j = 0; j < 16; j++) {
            int c = qc * 16 + j;
            float bb = g_bi3[g * 128 + c];
            float2 res = *(const float2*)(resp + (size_t)j * HW);
            float v0 = fmaxf(bb + res.x, 0.f);
            float v1 = fmaxf(bb + res.y, 0.f);
            *(float2*)(op + (size_t)j * HW) = make_float2(v0, v1);
        }
    }
}

// ---------------------------------------------------------------------------
extern "C" void kernel_launch(void* const* d_in, const int* in_sizes, int n_in,
                              void* d_out, int out_size) {
    const float* x    = (const float*)d_in[0];
    const float* mask = (const float*)d_in[1];
    const float* w1   = (const float*)d_in[2];
    const float* g1 = (const float*)d_in[3];
    const float* b1 = (const float*)d_in[4];
    const float* m1 = (const float*)d_in[5];
    const float* v1 = (const float*)d_in[6];
    const float* w2   = (const float*)d_in[7];
    const float* g2 = (const float*)d_in[8];
    const float* b2 = (const float*)d_in[9];
    const float* m2 = (const float*)d_in[10];
    const float* v2 = (const float*)d_in[11];
    const float* w3   = (const float*)d_in[12];
    const float* g3 = (const float*)d_in[13];
    const float* b3 = (const float*)d_in[14];
    const float* m3 = (const float*)d_in[15];
    const float* v3 = (const float*)d_in[16];
    float* out = (float*)d_out;

    bn_prep<<<1, 512>>>(g1, b1, m1, v1, g2, b2, m2, v2, g3, b3, m3, v3);

    k1<<<16 * 4 * 7 * 2, 224>>>(x, mask, w1);
    k2<<<16 * 4 * 7 * 2, 224>>>(mask, w2);
    k3<<<16 * 4 * 7 * 8, 224>>>(x, mask, w3, out);
}